// round 13
// baseline (speedup 1.0000x reference)
#include <cuda_runtime.h>

// Problem constants (fixed by setup_inputs)
#define B_  16
#define C_  64
#define IH_ 256
#define IW_ 256
#define CH_STRIDE (IH_*IW_)          // 65536
#define IMG_STRIDE (C_*CH_STRIDE)
#define CAP 4096                     // floats per smem channel buffer (16KB)

// Block = 32(ow) x 16(oh) output tile of one batch. 256 threads, 2 px/thread.
// Fast path: per-tile input bounding box staged in smem (double-buffered per
// channel); bilinear taps become branch-free LDS. Fallback: scattered-gather
// path with per-batch a x b lane patches. Fully-OOB tiles: pure zero stores.
__global__ __launch_bounds__(256)
void affine_fused_kernel(const float* __restrict__ inp,
                         const float* __restrict__ theta,
                         float* __restrict__ out,
                         float* __restrict__ vert)
{
    __shared__ float sbuf[2][CAP];

    const int blk  = blockIdx.x;
    const int b    = blk >> 7;               // 128 tiles per batch (8 x 16)
    const int tile = blk & 127;
    const int ow0  = (tile & 7)  << 5;
    const int oh0  = (tile >> 3) << 4;
    const int tid  = threadIdx.x;
    const int lane = tid & 31;
    const int wrp  = tid >> 5;               // 0..7

    // ---- vertices (fused; block 0 only, before any early-out) ----
    if (blk == 0 && tid < B_ * 4) {
        const int vb = tid >> 2;
        const int v  = tid & 3;
        const float vx = (v >= 2) ? 1.0f : -1.0f;
        const float vy = (v == 1 || v == 2) ? 1.0f : -1.0f;
        const float* tv = theta + vb * 6;
        const float ox = tv[0] * vx + tv[1] * vy + tv[2];
        const float oy = tv[3] * vx + tv[4] * vy + tv[5];
        vert[tid * 2 + 0] = (ox + 1.0f) * ((float)IW_ * 0.5f);
        vert[tid * 2 + 1] = (oy + 1.0f) * ((float)IH_ * 0.5f);
    }

    const float* tb = theta + b * 6;
    const float t00 = tb[0], t01 = tb[1], t02 = tb[2];
    const float t10 = tb[3], t11 = tb[4], t12 = tb[5];

    float* outb = out + (long long)b * IMG_STRIDE;

    // ---- tile input-space extents (ix,iy affine in (ow,oh)) ----
    const float ww0 = fmaf((float)ow0, 2.0f / 255.0f, -1.0f);
    const float hh0 = fmaf((float)oh0, 2.0f / 255.0f, -1.0f);
    const float ix00 = (fmaf(t00, ww0, fmaf(t01, hh0, t02)) + 1.0f) * 127.5f;
    const float iy00 = (fmaf(t10, ww0, fmaf(t11, hh0, t12)) + 1.0f) * 127.5f;
    const float ixmax = ix00 + 31.0f * fmaxf(t00, 0.0f) + 15.0f * fmaxf(t01, 0.0f);
    const float ixmin = ix00 + 31.0f * fminf(t00, 0.0f) + 15.0f * fminf(t01, 0.0f);
    const float iymax = iy00 + 31.0f * fmaxf(t10, 0.0f) + 15.0f * fmaxf(t11, 0.0f);
    const float iymin = iy00 + 31.0f * fminf(t10, 0.0f) + 15.0f * fminf(t11, 0.0f);

    const bool deadt = (ixmax <= -1.0f) || (ixmin >= 256.0f)
                    || (iymax <= -1.0f) || (iymin >= 256.0f);
    if (deadt) {
        float* o0 = outb + (oh0 + wrp    ) * IW_ + ow0 + lane;
        float* o1 = outb + (oh0 + wrp + 8) * IW_ + ow0 + lane;
        #pragma unroll 8
        for (int c = 0; c < C_; ++c) {
            __stcs(o0 + (long long)c * CH_STRIDE, 0.0f);
            __stcs(o1 + (long long)c * CH_STRIDE, 0.0f);
        }
        return;
    }

    // Clamped bbox covers every pixel's CLAMPED corner coords (extremes over
    // the whole tile, capped to [0,255]).
    const int xlo = max(0, (int)floorf(ixmin));
    const int xhi = min(IW_ - 1, (int)floorf(ixmax) + 1);
    const int ylo = max(0, (int)floorf(iymin));
    const int yhi = min(IH_ - 1, (int)floorf(iymax) + 1);
    const int rx  = xhi - xlo + 1;
    const int ny  = yhi - ylo + 1;
    const int rxp = rx | 1;                   // odd stride vs bank conflicts

    const float* base = inp + (long long)b * IMG_STRIDE;

    if (rxp * ny <= CAP) {
        // ================= smem-staged path =================
        int   s[2][4];
        float w[2][4];

        #pragma unroll
        for (int k = 0; k < 2; ++k) {
            const int oh_l = wrp + 8 * k;
            const int ow_l = lane;

            const float wwv = fmaf((float)(ow0 + ow_l), 2.0f / 255.0f, -1.0f);
            const float hhv = fmaf((float)(oh0 + oh_l), 2.0f / 255.0f, -1.0f);
            const float gx = fmaf(t00, wwv, fmaf(t01, hhv, t02));
            const float gy = fmaf(t10, wwv, fmaf(t11, hhv, t12));
            const float ix = (gx + 1.0f) * 0.5f * 255.0f;
            const float iy = (gy + 1.0f) * 0.5f * 255.0f;

            const float x0f = floorf(ix);
            const float y0f = floorf(iy);
            const float wx1 = ix - x0f;
            const float wy1 = iy - y0f;
            const float wx0 = 1.0f - wx1;
            const float wy0 = 1.0f - wy1;

            const bool inx0 = (x0f >=  0.0f) && (x0f <= 255.0f);
            const bool inx1 = (x0f >= -1.0f) && (x0f <= 254.0f);
            const bool iny0 = (y0f >=  0.0f) && (y0f <= 255.0f);
            const bool iny1 = (y0f >= -1.0f) && (y0f <= 254.0f);

            w[k][0] = (inx0 && iny0) ? wx0 * wy0 : 0.0f;
            w[k][1] = (inx1 && iny0) ? wx1 * wy0 : 0.0f;
            w[k][2] = (inx0 && iny1) ? wx0 * wy1 : 0.0f;
            w[k][3] = (inx1 && iny1) ? wx1 * wy1 : 0.0f;

            const int x0i = min(max((int)x0f,     0), IW_ - 1);
            const int x1i = min(max((int)x0f + 1, 0), IW_ - 1);
            const int y0i = min(max((int)y0f,     0), IH_ - 1);
            const int y1i = min(max((int)y0f + 1, 0), IH_ - 1);

            const int s00 = (y0i - ylo) * rxp + (x0i - xlo);
            const int dx  = x1i - x0i;                // 0 or 1
            const int dy  = (y1i - y0i) * rxp;        // 0 or rxp
            s[k][0] = s00;
            s[k][1] = s00 + dx;
            s[k][2] = s00 + dy;
            s[k][3] = s00 + dy + dx;
        }

        float* ob0 = outb + (oh0 + wrp    ) * IW_ + ow0 + lane;
        float* ob1 = outb + (oh0 + wrp + 8) * IW_ + ow0 + lane;

        // preload channel 0
        {
            const float* src0 = base + ylo * IW_ + xlo;
            for (int r = wrp; r < ny; r += 8) {
                const float* src = src0 + r * IW_;
                float* dst = &sbuf[0][r * rxp];
                for (int cc = lane; cc < rx; cc += 32)
                    dst[cc] = __ldg(src + cc);
            }
        }
        __syncthreads();

        #pragma unroll 1
        for (int c = 0; c < C_; ++c) {
            if (c + 1 < C_) {
                const float* src0 = base + (long long)(c + 1) * CH_STRIDE
                                         + ylo * IW_ + xlo;
                float* bufn = sbuf[(c + 1) & 1];
                for (int r = wrp; r < ny; r += 8) {
                    const float* src = src0 + r * IW_;
                    float* dst = bufn + r * rxp;
                    for (int cc = lane; cc < rx; cc += 32)
                        dst[cc] = __ldg(src + cc);
                }
            }
            const float* sb = sbuf[c & 1];
            float a0 =      w[0][0] * sb[s[0][0]];
            a0 = fmaf(w[0][1], sb[s[0][1]], a0);
            a0 = fmaf(w[0][2], sb[s[0][2]], a0);
            a0 = fmaf(w[0][3], sb[s[0][3]], a0);
            float a1 =      w[1][0] * sb[s[1][0]];
            a1 = fmaf(w[1][1], sb[s[1][1]], a1);
            a1 = fmaf(w[1][2], sb[s[1][2]], a1);
            a1 = fmaf(w[1][3], sb[s[1][3]], a1);
            __stcs(ob0 + (long long)c * CH_STRIDE, a0);
            __stcs(ob1 + (long long)c * CH_STRIDE, a1);
            __syncthreads();
        }
        return;
    }

    // ================= gather fallback (R12 path) =================
    const float at00 = fabsf(t00), at01 = fabsf(t01);
    const float at10 = fabsf(t10), at11 = fabsf(t11);
    int la_ = 2; float bestC = 1e30f;
    #pragma unroll
    for (int la = 2; la <= 5; ++la) {
        const float af = (float)(1 << la);
        const float bf = 32.0f / af;
        const float ly = fmaf(af, at10, fmaf(bf, at11, 1.0f));
        const float lx = fmaf(fmaf(af, at00, bf * at01), 0.03125f, 1.0f);
        const float c  = 4.0f * ly * lx + 32.0f / af;
        if (c <= bestC) { bestC = c; la_ = la; }
    }
    const int amask = (1 << la_) - 1;
    const int lb_   = 5 - la_;
    const int nxm1  = (32 >> la_) - 1;

    int   offs[2][4];
    float wgt [2][4];
    bool  any [2];
    int   ohl [2], owl[2];

    #pragma unroll
    for (int k = 0; k < 2; ++k) {
        const int p  = (wrp << 1) + k;
        const int px = p & nxm1;
        const int py = p >> lb_;
        const int oh_l = (py << lb_) + (lane >> la_);
        const int ow_l = (px << la_) + (lane & amask);
        ohl[k] = oh_l; owl[k] = ow_l;

        const float wwv = fmaf((float)(ow0 + ow_l), 2.0f / 255.0f, -1.0f);
        const float hhv = fmaf((float)(oh0 + oh_l), 2.0f / 255.0f, -1.0f);
        const float gx = fmaf(t00, wwv, fmaf(t01, hhv, t02));
        const float gy = fmaf(t10, wwv, fmaf(t11, hhv, t12));
        const float ix = (gx + 1.0f) * 0.5f * 255.0f;
        const float iy = (gy + 1.0f) * 0.5f * 255.0f;

        const float x0f = floorf(ix);
        const float y0f = floorf(iy);
        const float wx1 = ix - x0f;
        const float wy1 = iy - y0f;
        const float wx0 = 1.0f - wx1;
        const float wy0 = 1.0f - wy1;

        const bool inx0 = (x0f >=  0.0f) && (x0f <= 255.0f);
        const bool inx1 = (x0f >= -1.0f) && (x0f <= 254.0f);
        const bool iny0 = (y0f >=  0.0f) && (y0f <= 255.0f);
        const bool iny1 = (y0f >= -1.0f) && (y0f <= 254.0f);

        wgt[k][0] = (inx0 && iny0) ? wx0 * wy0 : 0.0f;
        wgt[k][1] = (inx1 && iny0) ? wx1 * wy0 : 0.0f;
        wgt[k][2] = (inx0 && iny1) ? wx0 * wy1 : 0.0f;
        wgt[k][3] = (inx1 && iny1) ? wx1 * wy1 : 0.0f;
        any[k] = (wgt[k][0] + wgt[k][1] + wgt[k][2] + wgt[k][3]) != 0.0f;

        const int x0i = min(max((int)x0f,     0), IW_ - 1);
        const int x1i = min(max((int)x0f + 1, 0), IW_ - 1);
        const int y0i = min(max((int)y0f,     0), IH_ - 1);
        const int y1i = min(max((int)y0f + 1, 0), IH_ - 1);

        offs[k][0] = y0i * IW_ + x0i;
        offs[k][1] = y0i * IW_ + x1i;
        offs[k][2] = y1i * IW_ + x0i;
        offs[k][3] = y1i * IW_ + x1i;
    }

    float* ob0 = outb + (oh0 + ohl[0]) * IW_ + ow0 + owl[0];
    float* ob1 = outb + (oh0 + ohl[1]) * IW_ + ow0 + owl[1];

    #pragma unroll 1
    for (int c0 = 0; c0 < C_; c0 += 2) {
        #pragma unroll
        for (int cc = 0; cc < 2; ++cc) {
            const float* ch = base + (long long)(c0 + cc) * CH_STRIDE;
            float a0 = 0.0f, a1 = 0.0f;
            if (any[0]) {
                a0 =      wgt[0][0] * __ldg(ch + offs[0][0]);
                a0 = fmaf(wgt[0][1], __ldg(ch + offs[0][1]), a0);
                a0 = fmaf(wgt[0][2], __ldg(ch + offs[0][2]), a0);
                a0 = fmaf(wgt[0][3], __ldg(ch + offs[0][3]), a0);
            }
            if (any[1]) {
                a1 =      wgt[1][0] * __ldg(ch + offs[1][0]);
                a1 = fmaf(wgt[1][1], __ldg(ch + offs[1][1]), a1);
                a1 = fmaf(wgt[1][2], __ldg(ch + offs[1][2]), a1);
                a1 = fmaf(wgt[1][3], __ldg(ch + offs[1][3]), a1);
            }
            __stcs(ob0 + (long long)(c0 + cc) * CH_STRIDE, a0);
            __stcs(ob1 + (long long)(c0 + cc) * CH_STRIDE, a1);
        }
    }
}

extern "C" void kernel_launch(void* const* d_in, const int* in_sizes, int n_in,
                              void* d_out, int out_size)
{
    const float* inp   = (const float*)d_in[0];
    const float* theta = (const float*)d_in[1];
    float* out = (float*)d_out;

    // Tuple output flattening: [B,C,OH,OW] image first, then [B,4,2] vertices.
    float* vert = out + (out_size - B_ * 4 * 2);

    affine_fused_kernel<<<B_ * 128, 256>>>(inp, theta, out, vert);
}

// round 14
// speedup vs baseline: 4.5524x; 4.5524x over previous
#include <cuda_runtime.h>

// Problem constants (fixed by setup_inputs)
#define B_  16
#define C_  64
#define IH_ 256
#define IW_ 256
#define CH_STRIDE (IH_*IW_)          // 65536
#define IMG_STRIDE (C_*CH_STRIDE)
#define CSPLIT 4                     // channel groups per tile
#define CGRP  (C_/CSPLIT)            // 16 channels per block

// Block = 32(ow) x 16(oh) output tile of one batch, ONE channel group of 16.
// 256 threads, 2 px/thread. Warp lane geometry = a x b patch (ab = 32),
// a chosen per batch from {4,8,16,32} by a gather-line + store-line cost
// model. Fully-OOB tiles short-circuit to a zero-store loop.
__global__ __launch_bounds__(256)
void affine_fused_kernel(const float* __restrict__ inp,
                         const float* __restrict__ theta,
                         float* __restrict__ out,
                         float* __restrict__ vert)
{
    const int blk  = blockIdx.x;
    const int b    = blk >> 9;               // 128 tiles * 4 csplits per batch
    const int tile = (blk >> 2) & 127;
    const int cs   = blk & 3;                // channel group
    const int ow0  = (tile & 7)  << 5;
    const int oh0  = (tile >> 3) << 4;
    const int tid  = threadIdx.x;
    const int lane = tid & 31;
    const int wrp  = tid >> 5;               // 0..7
    const int cbeg = cs * CGRP;

    // ---- vertices (fused; block 0 only, before any early-out) ----
    if (blk == 0 && tid < B_ * 4) {
        const int vb = tid >> 2;
        const int v  = tid & 3;
        const float vx = (v >= 2) ? 1.0f : -1.0f;
        const float vy = (v == 1 || v == 2) ? 1.0f : -1.0f;
        const float* tv = theta + vb * 6;
        const float ox = tv[0] * vx + tv[1] * vy + tv[2];
        const float oy = tv[3] * vx + tv[4] * vy + tv[5];
        vert[tid * 2 + 0] = (ox + 1.0f) * ((float)IW_ * 0.5f);
        vert[tid * 2 + 1] = (oy + 1.0f) * ((float)IH_ * 0.5f);
    }

    const float* tb = theta + b * 6;
    const float t00 = tb[0], t01 = tb[1], t02 = tb[2];
    const float t10 = tb[3], t11 = tb[4], t12 = tb[5];

    float* outb = out + (long long)b * IMG_STRIDE;

    // ---- tile-level OOB cull (ix,iy affine in (ow,oh)) ----
    {
        const float ww0 = fmaf((float)ow0, 2.0f / 255.0f, -1.0f);
        const float hh0 = fmaf((float)oh0, 2.0f / 255.0f, -1.0f);
        const float ix00 = (fmaf(t00, ww0, fmaf(t01, hh0, t02)) + 1.0f) * 127.5f;
        const float iy00 = (fmaf(t10, ww0, fmaf(t11, hh0, t12)) + 1.0f) * 127.5f;
        const float ixmax = ix00 + 31.0f * fmaxf(t00, 0.0f) + 15.0f * fmaxf(t01, 0.0f);
        const float ixmin = ix00 + 31.0f * fminf(t00, 0.0f) + 15.0f * fminf(t01, 0.0f);
        const float iymax = iy00 + 31.0f * fmaxf(t10, 0.0f) + 15.0f * fmaxf(t11, 0.0f);
        const float iymin = iy00 + 31.0f * fminf(t10, 0.0f) + 15.0f * fminf(t11, 0.0f);
        const bool dead = (ixmax <= -1.0f) || (ixmin >= 256.0f)
                       || (iymax <= -1.0f) || (iymin >= 256.0f);
        if (dead) {
            float* o0 = outb + (long long)cbeg * CH_STRIDE
                             + (oh0 + wrp    ) * IW_ + ow0 + lane;
            float* o1 = outb + (long long)cbeg * CH_STRIDE
                             + (oh0 + wrp + 8) * IW_ + ow0 + lane;
            #pragma unroll 8
            for (int c = 0; c < CGRP; ++c) {
                __stcs(o0 + (long long)c * CH_STRIDE, 0.0f);
                __stcs(o1 + (long long)c * CH_STRIDE, 0.0f);
            }
            return;
        }
    }

    // ---- per-batch patch shape: a x b, ab = 32, a in {4,8,16,32} ----
    const float at00 = fabsf(t00), at01 = fabsf(t01);
    const float at10 = fabsf(t10), at11 = fabsf(t11);
    int la_ = 2; float bestC = 1e30f;
    #pragma unroll
    for (int la = 2; la <= 5; ++la) {
        const float af = (float)(1 << la);
        const float bf = 32.0f / af;
        const float ly = fmaf(af, at10, fmaf(bf, at11, 1.0f));     // rows spanned
        const float lx = fmaf(fmaf(af, at00, bf * at01), 0.03125f, 1.0f); // lines/row
        const float c  = 4.0f * ly * lx + 32.0f / af;              // gathers + store
        if (c <= bestC) { bestC = c; la_ = la; }
    }
    const int amask = (1 << la_) - 1;
    const int lb_   = 5 - la_;                 // b = 1 << lb_
    const int nxm1  = (32 >> la_) - 1;         // patches across ow

    // ---- per-pixel precompute (k = 0,1) ----
    int   offs[2][4];
    float wgt [2][4];
    bool  any [2];
    int   ohl [2], owl[2];

    #pragma unroll
    for (int k = 0; k < 2; ++k) {
        const int p  = (wrp << 1) + k;         // patch index 0..15
        const int px = p & nxm1;
        const int py = p >> lb_;
        const int oh_l = (py << lb_) + (lane >> la_);
        const int ow_l = (px << la_) + (lane & amask);
        ohl[k] = oh_l; owl[k] = ow_l;

        const float wwv = fmaf((float)(ow0 + ow_l), 2.0f / 255.0f, -1.0f);
        const float hhv = fmaf((float)(oh0 + oh_l), 2.0f / 255.0f, -1.0f);

        const float gx = fmaf(t00, wwv, fmaf(t01, hhv, t02));
        const float gy = fmaf(t10, wwv, fmaf(t11, hhv, t12));

        const float ix = (gx + 1.0f) * 0.5f * 255.0f;   // align_corners=True
        const float iy = (gy + 1.0f) * 0.5f * 255.0f;

        const float x0f = floorf(ix);
        const float y0f = floorf(iy);
        const float wx1 = ix - x0f;
        const float wy1 = iy - y0f;
        const float wx0 = 1.0f - wx1;
        const float wy0 = 1.0f - wy1;

        const bool inx0 = (x0f >=  0.0f) && (x0f <= 255.0f);
        const bool inx1 = (x0f >= -1.0f) && (x0f <= 254.0f);
        const bool iny0 = (y0f >=  0.0f) && (y0f <= 255.0f);
        const bool iny1 = (y0f >= -1.0f) && (y0f <= 254.0f);

        wgt[k][0] = (inx0 && iny0) ? wx0 * wy0 : 0.0f;
        wgt[k][1] = (inx1 && iny0) ? wx1 * wy0 : 0.0f;
        wgt[k][2] = (inx0 && iny1) ? wx0 * wy1 : 0.0f;
        wgt[k][3] = (inx1 && iny1) ? wx1 * wy1 : 0.0f;
        any[k] = (wgt[k][0] + wgt[k][1] + wgt[k][2] + wgt[k][3]) != 0.0f;

        const int x0i = min(max((int)x0f,     0), IW_ - 1);
        const int x1i = min(max((int)x0f + 1, 0), IW_ - 1);
        const int y0i = min(max((int)y0f,     0), IH_ - 1);
        const int y1i = min(max((int)y0f + 1, 0), IH_ - 1);

        offs[k][0] = y0i * IW_ + x0i;
        offs[k][1] = y0i * IW_ + x1i;
        offs[k][2] = y1i * IW_ + x0i;
        offs[k][3] = y1i * IW_ + x1i;
    }

    const float* base = inp + (long long)b * IMG_STRIDE + (long long)cbeg * CH_STRIDE;
    float* ob0 = outb + (long long)cbeg * CH_STRIDE
                      + (oh0 + ohl[0]) * IW_ + ow0 + owl[0];
    float* ob1 = outb + (long long)cbeg * CH_STRIDE
                      + (oh0 + ohl[1]) * IW_ + ow0 + owl[1];

    #pragma unroll 1
    for (int c0 = 0; c0 < CGRP; c0 += 2) {
        #pragma unroll
        for (int cc = 0; cc < 2; ++cc) {
            const float* ch = base + (long long)(c0 + cc) * CH_STRIDE;
            float a0 = 0.0f, a1 = 0.0f;
            if (any[0]) {
                a0 =      wgt[0][0] * __ldg(ch + offs[0][0]);
                a0 = fmaf(wgt[0][1], __ldg(ch + offs[0][1]), a0);
                a0 = fmaf(wgt[0][2], __ldg(ch + offs[0][2]), a0);
                a0 = fmaf(wgt[0][3], __ldg(ch + offs[0][3]), a0);
            }
            if (any[1]) {
                a1 =      wgt[1][0] * __ldg(ch + offs[1][0]);
                a1 = fmaf(wgt[1][1], __ldg(ch + offs[1][1]), a1);
                a1 = fmaf(wgt[1][2], __ldg(ch + offs[1][2]), a1);
                a1 = fmaf(wgt[1][3], __ldg(ch + offs[1][3]), a1);
            }
            __stcs(ob0 + (long long)(c0 + cc) * CH_STRIDE, a0);
            __stcs(ob1 + (long long)(c0 + cc) * CH_STRIDE, a1);
        }
    }
}

extern "C" void kernel_launch(void* const* d_in, const int* in_sizes, int n_in,
                              void* d_out, int out_size)
{
    const float* inp   = (const float*)d_in[0];
    const float* theta = (const float*)d_in[1];
    float* out = (float*)d_out;

    // Tuple output flattening: [B,C,OH,OW] image first, then [B,4,2] vertices.
    float* vert = out + (out_size - B_ * 4 * 2);

    affine_fused_kernel<<<B_ * 128 * CSPLIT, 256>>>(inp, theta, out, vert);
}